// round 1
// baseline (speedup 1.0000x reference)
#include <cuda_runtime.h>
#include <cuda_bf16.h>
#include <cstdint>

#define N_NODES 100000
#define N_EDGES 1600000
#define F_IN 5
#define F_HID 64
#define F_OUT 72
#define NEG_SLOPE 0.2f

// ---------------- device scratch (static, no allocation) ----------------
__device__ float g_h[(size_t)N_NODES * F_HID];   // 25.6 MB
__device__ float g_as[N_NODES];
__device__ float g_ad[N_NODES];
__device__ float g_denom[N_NODES];
__device__ float g_selfexp[N_NODES];
__device__ float g_w[N_NODES];
__device__ float g_ex[N_EDGES];
__device__ int   g_src[N_EDGES];
__device__ int   g_dst[N_EDGES];
__device__ float g_pooled[F_HID];
__device__ int   g_idx32;   // 1 if edge_index is int32, 0 if int64

// ---------------- Kernel A: per-node h = x@W, a_s, a_d, init state ----------------
__global__ void kA(const float* __restrict__ x,
                   const float* __restrict__ W,
                   const float* __restrict__ att_src,
                   const float* __restrict__ att_dst,
                   const void*  __restrict__ ei) {
    __shared__ float sW[F_IN * F_HID];
    __shared__ float sas[F_HID], sad[F_HID];
    int tid = threadIdx.x;
    for (int i = tid; i < F_IN * F_HID; i += blockDim.x) sW[i] = W[i];
    if (tid < F_HID) { sas[tid] = att_src[tid]; sad[tid] = att_dst[tid]; }
    __syncthreads();

    if (blockIdx.x == 0) {
        if (tid < F_HID) g_pooled[tid] = 0.0f;
        if (tid == 0) {
            // dtype sniff: if edge_index is really int32, int64 reads combine
            // two ids -> values >= 2^32 >> N_NODES almost surely.
            const long long* e64 = (const long long*)ei;
            int flag = 0;
            for (int i = 0; i < 64; i++) {
                long long v = e64[i];
                if (v < 0 || v >= (long long)N_NODES) flag = 1;
            }
            g_idx32 = flag;
        }
    }

    int warp = tid >> 5, lane = tid & 31;
    int n = blockIdx.x * (blockDim.x >> 5) + warp;
    if (n >= N_NODES) return;

    float xv = (lane < F_IN) ? x[(size_t)n * F_IN + lane] : 0.0f;
    float xk[F_IN];
#pragma unroll
    for (int k = 0; k < F_IN; k++) xk[k] = __shfl_sync(0xffffffffu, xv, k);

    float h0 = 0.0f, h1 = 0.0f;
#pragma unroll
    for (int k = 0; k < F_IN; k++) {
        h0 += xk[k] * sW[k * F_HID + lane];
        h1 += xk[k] * sW[k * F_HID + lane + 32];
    }
    g_h[(size_t)n * F_HID + lane]      = h0;
    g_h[(size_t)n * F_HID + lane + 32] = h1;

    float as = h0 * sas[lane] + h1 * sas[lane + 32];
    float ad = h0 * sad[lane] + h1 * sad[lane + 32];
#pragma unroll
    for (int o = 16; o > 0; o >>= 1) {
        as += __shfl_xor_sync(0xffffffffu, as, o);
        ad += __shfl_xor_sync(0xffffffffu, ad, o);
    }
    if (lane == 0) {
        g_as[n] = as;
        g_ad[n] = ad;
        float es = as + ad;                       // self-loop raw attention
        es = es > 0.0f ? es : NEG_SLOPE * es;     // LeakyReLU
        float se = __expf(es);
        g_denom[n]   = se;    // denom starts with the self-loop term
        g_selfexp[n] = se;
        g_w[n]       = 0.0f;
    }
}

// ---------------- Kernel B: per-edge exp + denom accumulation ----------------
__global__ void kB(const void* __restrict__ ei) {
    int e = blockIdx.x * blockDim.x + threadIdx.x;
    if (e >= N_EDGES) return;
    int s, d;
    if (g_idx32) {
        const int* p = (const int*)ei;
        s = p[e]; d = p[N_EDGES + e];
    } else {
        const long long* p = (const long long*)ei;
        s = (int)p[e]; d = (int)p[N_EDGES + e];
    }
    float ev = g_as[s] + g_ad[d];
    ev = ev > 0.0f ? ev : NEG_SLOPE * ev;
    float ex = __expf(ev);
    g_ex[e]  = ex;
    g_src[e] = s;
    g_dst[e] = d;
    atomicAdd(&g_denom[d], ex);
}

// ---------------- Kernel C: per-edge alpha -> per-source weight ----------------
__global__ void kC() {
    int e = blockIdx.x * blockDim.x + threadIdx.x;
    if (e >= N_EDGES) return;
    float alpha = g_ex[e] / (g_denom[g_dst[e]] + 1e-16f);
    atomicAdd(&g_w[g_src[e]], alpha);
}

// ---------------- Kernel D: pooled[f] += sum_n w_total[n] * h[n][f] ----------------
__global__ void kD() {
    int f = threadIdx.x & (F_HID - 1);
    int g = threadIdx.x >> 6;                        // group within block (0..3)
    int groups_per_block = blockDim.x >> 6;
    int gidx   = blockIdx.x * groups_per_block + g;
    int stride = gridDim.x * groups_per_block;

    float acc = 0.0f;
    for (int n = gidx; n < N_NODES; n += stride) {
        float wn = g_w[n] + g_selfexp[n] / (g_denom[n] + 1e-16f);
        acc += wn * g_h[(size_t)n * F_HID + f];
    }
    __shared__ float s[256];
    s[threadIdx.x] = acc;
    __syncthreads();
    if (threadIdx.x < F_HID) {
        float v = s[threadIdx.x] + s[threadIdx.x + 64] +
                  s[threadIdx.x + 128] + s[threadIdx.x + 192];
        atomicAdd(&g_pooled[threadIdx.x], v);
    }
}

// ---------------- Kernel E: mean + bias + FC + ReLU ----------------
__global__ void kE(const float* __restrict__ b_gat,
                   const float* __restrict__ W_fc,
                   const float* __restrict__ b_fc,
                   float* __restrict__ out) {
    __shared__ float pool[F_HID];
    int t = threadIdx.x;
    if (t < F_HID) pool[t] = g_pooled[t] * (1.0f / (float)N_NODES) + b_gat[t];
    __syncthreads();
    if (t < F_OUT) {
        float acc = b_fc[t];
#pragma unroll
        for (int f = 0; f < F_HID; f++) acc += pool[f] * W_fc[f * F_OUT + t];
        out[t] = fmaxf(acc, 0.0f);
    }
}

// ---------------- launch ----------------
extern "C" void kernel_launch(void* const* d_in, const int* in_sizes, int n_in,
                              void* d_out, int out_size) {
    const float* x       = (const float*)d_in[0];
    const void*  ei      = d_in[1];                 // int64 or int32, sniffed in kA
    const float* W       = (const float*)d_in[2];
    const float* att_src = (const float*)d_in[3];
    const float* att_dst = (const float*)d_in[4];
    const float* b_gat   = (const float*)d_in[5];
    const float* W_fc    = (const float*)d_in[6];
    const float* b_fc    = (const float*)d_in[7];
    float* out = (float*)d_out;

    // A: 8 nodes/block (warp per node)
    int blocksA = (N_NODES + 7) / 8;
    kA<<<blocksA, 256>>>(x, W, att_src, att_dst, ei);

    int blocksE_ = (N_EDGES + 255) / 256;
    kB<<<blocksE_, 256>>>(ei);
    kC<<<blocksE_, 256>>>();

    kD<<<296, 256>>>();
    kE<<<1, 128>>>(b_gat, W_fc, b_fc, out);
}

// round 5
// speedup vs baseline: 1.7519x; 1.7519x over previous
#include <cuda_runtime.h>
#include <cuda_bf16.h>
#include <cstdint>

#define N_NODES 100000
#define N_EDGES 1600000
#define F_IN 5
#define F_HID 64
#define F_OUT 72
#define NEG_SLOPE 0.2f

// ---------------- device scratch (static, no allocation) ----------------
__device__ float g_as[N_NODES];       // x[n] . (W @ att_src)
__device__ float g_ad[N_NODES];       // x[n] . (W @ att_dst)
__device__ float g_denom[N_NODES];    // softmax denom per dst (init = self-loop exp)
__device__ float g_selfexp[N_NODES];  // self-loop exp term
__device__ float g_w[N_NODES];        // sum of alpha over edges with src = n
__device__ float g_pool5[F_IN];       // sum_n w_total[n] * x[n, :]  (5 floats)
__device__ int   g_idx32;             // 1 if edge_index arrived as int32

// ---------------- Kernel A: per-node attention halves + init ----------------
__global__ void kA(const float* __restrict__ x,
                   const float* __restrict__ W,
                   const float* __restrict__ att_src,
                   const float* __restrict__ att_dst,
                   const void*  __restrict__ ei) {
    __shared__ float ws[F_IN], wd[F_IN];
    int tid = threadIdx.x;
    if (tid < F_IN) {
        float s = 0.f, d = 0.f;
#pragma unroll
        for (int f = 0; f < F_HID; f++) {
            float w = W[tid * F_HID + f];
            s += w * att_src[f];
            d += w * att_dst[f];
        }
        ws[tid] = s; wd[tid] = d;
    }
    if (blockIdx.x == 0) {
        if (tid < F_IN) g_pool5[tid] = 0.0f;
        if (tid == 32) {
            // dtype sniff: int32 data read as int64 gives values >= 2^32 or <0
            const long long* e64 = (const long long*)ei;
            int flag = 0;
            for (int i = 0; i < 64; i++) {
                long long v = e64[i];
                if (v < 0 || v >= (long long)N_NODES) flag = 1;
            }
            g_idx32 = flag;
        }
    }
    __syncthreads();

    int n = blockIdx.x * blockDim.x + tid;
    if (n >= N_NODES) return;

    const float* xr = x + (size_t)n * F_IN;
    float x0 = xr[0], x1 = xr[1], x2 = xr[2], x3 = xr[3], x4 = xr[4];
    float as = x0*ws[0] + x1*ws[1] + x2*ws[2] + x3*ws[3] + x4*ws[4];
    float ad = x0*wd[0] + x1*wd[1] + x2*wd[2] + x3*wd[3] + x4*wd[4];
    g_as[n] = as;
    g_ad[n] = ad;
    float es = as + ad;
    es = es > 0.0f ? es : NEG_SLOPE * es;   // LeakyReLU
    float se = __expf(es);
    g_denom[n]   = se;                       // denom starts with self-loop term
    g_selfexp[n] = se;
    g_w[n]       = 0.0f;
}

// ---------------- Kernel B: per-edge exp -> denom accumulation ----------------
__global__ void kB(const void* __restrict__ ei) {
    int e0 = (blockIdx.x * blockDim.x + threadIdx.x) * 2;
    if (e0 >= N_EDGES) return;
    int s0, s1, d0, d1;
    if (g_idx32) {
        const int2* ps = (const int2*)((const int*)ei + e0);
        const int2* pd = (const int2*)((const int*)ei + N_EDGES + e0);
        int2 sv = *ps, dv = *pd;
        s0 = sv.x; s1 = sv.y; d0 = dv.x; d1 = dv.y;
    } else {
        const ulonglong2* ps = (const ulonglong2*)((const long long*)ei + e0);
        const ulonglong2* pd = (const ulonglong2*)((const long long*)ei + N_EDGES + e0);
        ulonglong2 sv = *ps, dv = *pd;
        s0 = (int)sv.x; s1 = (int)sv.y; d0 = (int)dv.x; d1 = (int)dv.y;
    }
    float e0v = g_as[s0] + g_ad[d0];
    float e1v = g_as[s1] + g_ad[d1];
    e0v = e0v > 0.0f ? e0v : NEG_SLOPE * e0v;
    e1v = e1v > 0.0f ? e1v : NEG_SLOPE * e1v;
    atomicAdd(&g_denom[d0], __expf(e0v));
    atomicAdd(&g_denom[d1], __expf(e1v));
}

// ---------------- Kernel C: per-edge alpha -> per-source weight ----------------
__global__ void kC(const void* __restrict__ ei) {
    int e0 = (blockIdx.x * blockDim.x + threadIdx.x) * 2;
    if (e0 >= N_EDGES) return;
    int s0, s1, d0, d1;
    if (g_idx32) {
        const int2* ps = (const int2*)((const int*)ei + e0);
        const int2* pd = (const int2*)((const int*)ei + N_EDGES + e0);
        int2 sv = *ps, dv = *pd;
        s0 = sv.x; s1 = sv.y; d0 = dv.x; d1 = dv.y;
    } else {
        const ulonglong2* ps = (const ulonglong2*)((const long long*)ei + e0);
        const ulonglong2* pd = (const ulonglong2*)((const long long*)ei + N_EDGES + e0);
        ulonglong2 sv = *ps, dv = *pd;
        s0 = (int)sv.x; s1 = (int)sv.y; d0 = (int)dv.x; d1 = (int)dv.y;
    }
    float e0v = g_as[s0] + g_ad[d0];
    float e1v = g_as[s1] + g_ad[d1];
    e0v = e0v > 0.0f ? e0v : NEG_SLOPE * e0v;
    e1v = e1v > 0.0f ? e1v : NEG_SLOPE * e1v;
    float a0 = __expf(e0v) / (g_denom[d0] + 1e-16f);
    float a1 = __expf(e1v) / (g_denom[d1] + 1e-16f);
    atomicAdd(&g_w[s0], a0);
    atomicAdd(&g_w[s1], a1);
}

// ---------------- Kernel D: pool5[k] = sum_n w_total[n] * x[n][k] ----------------
__global__ void kD(const float* __restrict__ x) {
    int n = blockIdx.x * blockDim.x + threadIdx.x;
    float acc[F_IN] = {0.f, 0.f, 0.f, 0.f, 0.f};
    if (n < N_NODES) {
        float wn = g_w[n] + g_selfexp[n] / (g_denom[n] + 1e-16f);
        const float* xr = x + (size_t)n * F_IN;
#pragma unroll
        for (int k = 0; k < F_IN; k++) acc[k] = wn * xr[k];
    }
#pragma unroll
    for (int k = 0; k < F_IN; k++)
#pragma unroll
        for (int o = 16; o > 0; o >>= 1)
            acc[k] += __shfl_xor_sync(0xffffffffu, acc[k], o);

    __shared__ float s[8][F_IN];
    int warp = threadIdx.x >> 5, lane = threadIdx.x & 31;
    if (lane < F_IN) s[warp][lane] = acc[lane];
    __syncthreads();
    if (threadIdx.x < F_IN) {
        float v = 0.f;
#pragma unroll
        for (int wdx = 0; wdx < 8; wdx++) v += s[wdx][threadIdx.x];
        atomicAdd(&g_pool5[threadIdx.x], v);
    }
}

// ---------------- Kernel E: pool5 -> pooled64 -> FC -> ReLU ----------------
__global__ void kE(const float* __restrict__ W,
                   const float* __restrict__ b_gat,
                   const float* __restrict__ W_fc,
                   const float* __restrict__ b_fc,
                   float* __restrict__ out) {
    __shared__ float p64[F_HID];
    int t = threadIdx.x;
    if (t < F_HID) {
        float acc = b_gat[t];
        const float invN = 1.0f / (float)N_NODES;
#pragma unroll
        for (int k = 0; k < F_IN; k++)
            acc += (g_pool5[k] * invN) * W[k * F_HID + t];
        p64[t] = acc;
    }
    __syncthreads();
    if (t < F_OUT) {
        float acc = b_fc[t];
#pragma unroll
        for (int f = 0; f < F_HID; f++) acc += p64[f] * W_fc[f * F_OUT + t];
        out[t] = fmaxf(acc, 0.0f);
    }
}

// ---------------- launch ----------------
extern "C" void kernel_launch(void* const* d_in, const int* in_sizes, int n_in,
                              void* d_out, int out_size) {
    const float* x       = (const float*)d_in[0];
    const void*  ei      = d_in[1];
    const float* W       = (const float*)d_in[2];
    const float* att_src = (const float*)d_in[3];
    const float* att_dst = (const float*)d_in[4];
    const float* b_gat   = (const float*)d_in[5];
    const float* W_fc    = (const float*)d_in[6];
    const float* b_fc    = (const float*)d_in[7];
    float* out = (float*)d_out;

    int blocksN = (N_NODES + 255) / 256;
    int blocksE = (N_EDGES / 2 + 255) / 256;

    kA<<<blocksN, 256>>>(x, W, att_src, att_dst, ei);
    kB<<<blocksE, 256>>>(ei);
    kC<<<blocksE, 256>>>(ei);
    kD<<<blocksN, 256>>>(x);
    kE<<<1, 128>>>(W, b_gat, W_fc, b_fc, out);
}

// round 6
// speedup vs baseline: 1.9939x; 1.1381x over previous
#include <cuda_runtime.h>
#include <cuda_bf16.h>
#include <cstdint>

#define N_NODES 100000
#define N_EDGES 1600000
#define F_IN 5
#define F_HID 64
#define F_OUT 72
#define NEG_SLOPE 0.2f

// ---------------- device scratch (static, no allocation) ----------------
__device__ float g_as[N_NODES];       // x[n] . (W @ att_src)
__device__ float g_ad[N_NODES];       // x[n] . (W @ att_dst)
__device__ float g_denom[N_NODES];    // softmax denom per dst (init = self-loop exp)
__device__ float g_selfexp[N_NODES];  // self-loop exp term
__device__ float g_w[N_NODES];        // sum of alpha over edges with src = n
__device__ float g_ex[N_EDGES];       // per-edge exp (written kB, streamed kC)
__device__ float g_pool5[F_IN];       // sum_n w_total[n] * x[n, :]
__device__ int   g_idx32;             // 1 if edge_index arrived as int32
__device__ unsigned g_ticket = 0;     // last-block flag for fused kDE

// ---------------- Kernel A: per-node attention halves + init ----------------
__global__ void kA(const float* __restrict__ x,
                   const float* __restrict__ W,
                   const float* __restrict__ att_src,
                   const float* __restrict__ att_dst,
                   const void*  __restrict__ ei) {
    __shared__ float ws[F_IN], wd[F_IN];
    int tid = threadIdx.x;
    if (tid < F_IN) {
        float s = 0.f, d = 0.f;
#pragma unroll
        for (int f = 0; f < F_HID; f++) {
            float w = W[tid * F_HID + f];
            s += w * att_src[f];
            d += w * att_dst[f];
        }
        ws[tid] = s; wd[tid] = d;
    }
    if (blockIdx.x == 0) {
        if (tid < F_IN) g_pool5[tid] = 0.0f;
        if (tid == 32) {
            // dtype sniff: int32 data read as int64 gives values >= 2^32 or < 0
            const long long* e64 = (const long long*)ei;
            int flag = 0;
            for (int i = 0; i < 64; i++) {
                long long v = e64[i];
                if (v < 0 || v >= (long long)N_NODES) flag = 1;
            }
            g_idx32 = flag;
        }
    }
    __syncthreads();

    int n = blockIdx.x * blockDim.x + tid;
    if (n >= N_NODES) return;

    const float* xr = x + (size_t)n * F_IN;
    float x0 = xr[0], x1 = xr[1], x2 = xr[2], x3 = xr[3], x4 = xr[4];
    float as = x0*ws[0] + x1*ws[1] + x2*ws[2] + x3*ws[3] + x4*ws[4];
    float ad = x0*wd[0] + x1*wd[1] + x2*wd[2] + x3*wd[3] + x4*wd[4];
    g_as[n] = as;
    g_ad[n] = ad;
    float es = as + ad;
    es = es > 0.0f ? es : NEG_SLOPE * es;   // LeakyReLU
    float se = __expf(es);
    g_denom[n]   = se;                       // denom starts with self-loop term
    g_selfexp[n] = se;
    g_w[n]       = 0.0f;
}

// ---------------- edge index loader: 4 edges per thread ----------------
__device__ __forceinline__ void load4(const void* __restrict__ ei, int e0,
                                      int (&s)[4], int (&d)[4]) {
    if (g_idx32) {
        int4 sv = *(const int4*)((const int*)ei + e0);
        int4 dv = *(const int4*)((const int*)ei + N_EDGES + e0);
        s[0] = sv.x; s[1] = sv.y; s[2] = sv.z; s[3] = sv.w;
        d[0] = dv.x; d[1] = dv.y; d[2] = dv.z; d[3] = dv.w;
    } else {
        const long long* b = (const long long*)ei;
        ulonglong2 sa = *(const ulonglong2*)(b + e0);
        ulonglong2 sb = *(const ulonglong2*)(b + e0 + 2);
        ulonglong2 da = *(const ulonglong2*)(b + N_EDGES + e0);
        ulonglong2 db = *(const ulonglong2*)(b + N_EDGES + e0 + 2);
        s[0] = (int)sa.x; s[1] = (int)sa.y; s[2] = (int)sb.x; s[3] = (int)sb.y;
        d[0] = (int)da.x; d[1] = (int)da.y; d[2] = (int)db.x; d[3] = (int)db.y;
    }
}

// ---------------- Kernel B: per-edge exp -> g_ex stream + denom atomics ----------------
__global__ void kB(const void* __restrict__ ei) {
    int e0 = (blockIdx.x * blockDim.x + threadIdx.x) * 4;
    if (e0 >= N_EDGES) return;
    int s[4], d[4];
    load4(ei, e0, s, d);

    float asv[4], adv[4];
#pragma unroll
    for (int i = 0; i < 4; i++) { asv[i] = g_as[s[i]]; adv[i] = g_ad[d[i]]; }

    float ex[4];
#pragma unroll
    for (int i = 0; i < 4; i++) {
        float ev = asv[i] + adv[i];
        ev = ev > 0.0f ? ev : NEG_SLOPE * ev;
        ex[i] = __expf(ev);
    }
    *(float4*)&g_ex[e0] = make_float4(ex[0], ex[1], ex[2], ex[3]);
#pragma unroll
    for (int i = 0; i < 4; i++) atomicAdd(&g_denom[d[i]], ex[i]);
}

// ---------------- Kernel C: alpha = ex/denom[dst] -> w[src] atomics ----------------
__global__ void kC(const void* __restrict__ ei) {
    int e0 = (blockIdx.x * blockDim.x + threadIdx.x) * 4;
    if (e0 >= N_EDGES) return;
    int s[4], d[4];
    load4(ei, e0, s, d);

    float4 exv = *(const float4*)&g_ex[e0];
    float ex[4] = {exv.x, exv.y, exv.z, exv.w};

    float dn[4];
#pragma unroll
    for (int i = 0; i < 4; i++) dn[i] = g_denom[d[i]];
#pragma unroll
    for (int i = 0; i < 4; i++)
        atomicAdd(&g_w[s[i]], ex[i] / (dn[i] + 1e-16f));
}

// ---------------- Kernel DE: weighted pool over x, then FC epilogue ----------------
__global__ void kDE(const float* __restrict__ x,
                    const float* __restrict__ W,
                    const float* __restrict__ b_gat,
                    const float* __restrict__ W_fc,
                    const float* __restrict__ b_fc,
                    float* __restrict__ out) {
    int n = blockIdx.x * blockDim.x + threadIdx.x;
    float acc[F_IN] = {0.f, 0.f, 0.f, 0.f, 0.f};
    if (n < N_NODES) {
        float wn = g_w[n] + g_selfexp[n] / (g_denom[n] + 1e-16f);
        const float* xr = x + (size_t)n * F_IN;
#pragma unroll
        for (int k = 0; k < F_IN; k++) acc[k] = wn * xr[k];
    }
#pragma unroll
    for (int k = 0; k < F_IN; k++)
#pragma unroll
        for (int o = 16; o > 0; o >>= 1)
            acc[k] += __shfl_xor_sync(0xffffffffu, acc[k], o);

    __shared__ float s[8][F_IN];
    int warp = threadIdx.x >> 5, lane = threadIdx.x & 31;
    if (lane < F_IN) s[warp][lane] = acc[lane];
    __syncthreads();
    if (threadIdx.x < F_IN) {
        float v = 0.f;
#pragma unroll
        for (int wdx = 0; wdx < 8; wdx++) v += s[wdx][threadIdx.x];
        atomicAdd(&g_pool5[threadIdx.x], v);
    }

    // ---- last-block epilogue (fused kE) ----
    __threadfence();
    __shared__ int is_last;
    if (threadIdx.x == 0)
        is_last = (atomicAdd(&g_ticket, 1u) == (unsigned)gridDim.x - 1u);
    __syncthreads();
    if (!is_last) return;

    __shared__ float p64[F_HID];
    int t = threadIdx.x;
    if (t == 0) g_ticket = 0;                // reset for next graph replay
    if (t < F_HID) {
        float a = b_gat[t];
        const float invN = 1.0f / (float)N_NODES;
#pragma unroll
        for (int k = 0; k < F_IN; k++)
            a += (g_pool5[k] * invN) * W[k * F_HID + t];
        p64[t] = a;
    }
    __syncthreads();
    if (t < F_OUT) {
        float a = b_fc[t];
#pragma unroll
        for (int f = 0; f < F_HID; f++) a += p64[f] * W_fc[f * F_OUT + t];
        out[t] = fmaxf(a, 0.0f);
    }
}

// ---------------- launch ----------------
extern "C" void kernel_launch(void* const* d_in, const int* in_sizes, int n_in,
                              void* d_out, int out_size) {
    const float* x       = (const float*)d_in[0];
    const void*  ei      = d_in[1];
    const float* W       = (const float*)d_in[2];
    const float* att_src = (const float*)d_in[3];
    const float* att_dst = (const float*)d_in[4];
    const float* b_gat   = (const float*)d_in[5];
    const float* W_fc    = (const float*)d_in[6];
    const float* b_fc    = (const float*)d_in[7];
    float* out = (float*)d_out;

    int blocksN = (N_NODES + 255) / 256;
    int blocksE = (N_EDGES / 4 + 255) / 256;

    kA<<<blocksN, 256>>>(x, W, att_src, att_dst, ei);
    kB<<<blocksE, 256>>>(ei);
    kC<<<blocksE, 256>>>(ei);
    kDE<<<blocksN, 256>>>(x, W, b_gat, W_fc, b_fc, out);
}